// round 1
// baseline (speedup 1.0000x reference)
#include <cuda_runtime.h>
#include <math.h>

#define NROWS 65536
#define D 256
#define NC 1000
#define MROWS 128
#define EP 260           // Es pitch (floats), 260%4==0 for float4, breaks bank ties
#define TPB 512

// Scratch (device globals: no allocation allowed)
__device__ float g_sums[NC * D];
__device__ float g_counts[NC];
__device__ float g_chat[NC * D];
__device__ float g_v[D];
__device__ float g_M[D * D];
__device__ float g_loss;

// ---------------------------------------------------------------------------
__global__ void k_zero() {
    int i = blockIdx.x * 256 + threadIdx.x;
    if (i < NC * D) g_sums[i] = 0.f;
    if (i < NC) g_counts[i] = 0.f;
    if (i < D) g_v[i] = 0.f;
    if (i == 0) g_loss = 0.f;
}

// ---------------------------------------------------------------------------
// Normalize rows (warp per row) and accumulate per-class sums/counts.
__global__ void k_normacc(const float* __restrict__ emb,
                          const int* __restrict__ labels) {
    int warp = threadIdx.x >> 5, lane = threadIdx.x & 31;
    int row = blockIdx.x * 8 + warp;
    const float* e = emb + (size_t)row * D;

    float4 x0 = *(const float4*)(e + lane * 4);
    float4 x1 = *(const float4*)(e + 128 + lane * 4);
    float ss = x0.x * x0.x + x0.y * x0.y + x0.z * x0.z + x0.w * x0.w
             + x1.x * x1.x + x1.y * x1.y + x1.z * x1.z + x1.w * x1.w;
    #pragma unroll
    for (int off = 16; off; off >>= 1)
        ss += __shfl_xor_sync(0xffffffffu, ss, off);

    float rn = 1.f / fmaxf(sqrtf(ss), 1e-12f);
    int lab = labels[row];
    float* dst = g_sums + (size_t)lab * D;
    atomicAdd(dst + lane * 4 + 0,       x0.x * rn);
    atomicAdd(dst + lane * 4 + 1,       x0.y * rn);
    atomicAdd(dst + lane * 4 + 2,       x0.z * rn);
    atomicAdd(dst + lane * 4 + 3,       x0.w * rn);
    atomicAdd(dst + 128 + lane * 4 + 0, x1.x * rn);
    atomicAdd(dst + 128 + lane * 4 + 1, x1.y * rn);
    atomicAdd(dst + 128 + lane * 4 + 2, x1.z * rn);
    atomicAdd(dst + 128 + lane * 4 + 3, x1.w * rn);
    if (lane == 0) atomicAdd(&g_counts[lab], 1.f);
}

// ---------------------------------------------------------------------------
// Per-class: center = sum/max(count,1); chat = center/max(||center||,1e-8); v += chat
__global__ void k_centers() {
    int c = blockIdx.x, t = threadIdx.x;
    float cnt = g_counts[c];
    float center = g_sums[(size_t)c * D + t] / fmaxf(cnt, 1.f);

    float ss = center * center;
    #pragma unroll
    for (int off = 16; off; off >>= 1)
        ss += __shfl_xor_sync(0xffffffffu, ss, off);
    __shared__ float wsum[8];
    __shared__ float denom_s;
    if ((t & 31) == 0) wsum[t >> 5] = ss;
    __syncthreads();
    if (t == 0) {
        float tot = 0.f;
        #pragma unroll
        for (int w = 0; w < 8; w++) tot += wsum[w];
        denom_s = fmaxf(sqrtf(tot), 1e-8f);
    }
    __syncthreads();
    float ch = center / denom_s;
    g_chat[(size_t)c * D + t] = ch;
    atomicAdd(&g_v[t], ch);
}

// ---------------------------------------------------------------------------
// M = Chat^T Chat   (256x256, K=1000). 64 blocks x 4 rows each.
__global__ void k_M() {
    int b = threadIdx.x;
    int a0 = blockIdx.x * 4;
    float acc0 = 0.f, acc1 = 0.f, acc2 = 0.f, acc3 = 0.f;
    #pragma unroll 4
    for (int j = 0; j < NC; j++) {
        const float* row = g_chat + (size_t)j * D;
        float cb = row[b];
        acc0 += row[a0 + 0] * cb;
        acc1 += row[a0 + 1] * cb;
        acc2 += row[a0 + 2] * cb;
        acc3 += row[a0 + 3] * cb;
    }
    g_M[(size_t)(a0 + 0) * D + b] = acc0;
    g_M[(size_t)(a0 + 1) * D + b] = acc1;
    g_M[(size_t)(a0 + 2) * D + b] = acc2;
    g_M[(size_t)(a0 + 3) * D + b] = acc3;
}

// ---------------------------------------------------------------------------
// Main fused kernel: per 128-row tile compute T = E*M (4 x 64-col chunks),
// fold into S2 = e^T M e, plus S1 = e.v, slab = e.chat[label], row norm, loss.
__global__ __launch_bounds__(TPB, 1)
void k_main(const float* __restrict__ emb, const int* __restrict__ labels) {
    extern __shared__ float sh[];
    float* Es    = sh;                    // MROWS*EP   = 33280
    float* Ms    = Es + MROWS * EP;       // 256*64     = 16384
    float* vsh   = Ms + 256 * 64;         // 256
    float* s2row = vsh + 256;             // 128
    float* redA  = s2row + 128;           // 512
    float* redB  = redA + 512;            // 512
    float* redC  = redB + 512;            // 512
    int*   labsh = (int*)(redC + 512);    // 128
    float* lsum  = (float*)(labsh + 128); // 4

    int t = threadIdx.x;
    int row0 = blockIdx.x * MROWS;

    // Load E tile [128 x 256] (row-major, pitch EP)
    #pragma unroll
    for (int i = 0; i < 16; i++) {
        int idx = t + i * TPB;            // float4 index, 0..8191
        int r = idx >> 6, c4 = (idx & 63) << 2;
        float4 x = *(const float4*)(emb + (size_t)(row0 + r) * D + c4);
        *(float4*)(Es + r * EP + c4) = x;
    }
    if (t < 256) vsh[t] = g_v[t];
    if (t < 128) labsh[t] = labels[row0 + t];

    int tx = t & 15, ty = t >> 4;
    float s2p[4] = {0.f, 0.f, 0.f, 0.f};

    for (int dc = 0; dc < 4; dc++) {
        __syncthreads();
        // Load M chunk [256 x 64]
        #pragma unroll
        for (int i = 0; i < 8; i++) {
            int idx = t + i * TPB;        // float4 index, 0..4095
            int k = idx >> 4, c4 = (idx & 15) << 2;
            *(float4*)(Ms + k * 64 + c4) =
                *(const float4*)(g_M + (size_t)k * D + dc * 64 + c4);
        }
        __syncthreads();

        float acc[4][4] = {};
        const float* arow = Es + (ty * 4) * EP;
        #pragma unroll 4
        for (int k = 0; k < 256; k++) {
            float4 b = *(const float4*)(Ms + k * 64 + tx * 4);
            float a0 = arow[k];
            float a1 = arow[EP + k];
            float a2 = arow[2 * EP + k];
            float a3 = arow[3 * EP + k];
            acc[0][0] += a0 * b.x; acc[0][1] += a0 * b.y; acc[0][2] += a0 * b.z; acc[0][3] += a0 * b.w;
            acc[1][0] += a1 * b.x; acc[1][1] += a1 * b.y; acc[1][2] += a1 * b.z; acc[1][3] += a1 * b.w;
            acc[2][0] += a2 * b.x; acc[2][1] += a2 * b.y; acc[2][2] += a2 * b.z; acc[2][3] += a2 * b.w;
            acc[3][0] += a3 * b.x; acc[3][1] += a3 * b.y; acc[3][2] += a3 * b.z; acc[3][3] += a3 * b.w;
        }
        // Fold tile into S2 partials: t[r][d] * e[r][d]
        #pragma unroll
        for (int i = 0; i < 4; i++) {
            float4 e4 = *(const float4*)(Es + (ty * 4 + i) * EP + dc * 64 + tx * 4);
            s2p[i] += acc[i][0] * e4.x + acc[i][1] * e4.y
                    + acc[i][2] * e4.z + acc[i][3] * e4.w;
        }
    }

    // Reduce S2 partials across the 16 tx lanes (xor<16 stays in same ty group)
    #pragma unroll
    for (int i = 0; i < 4; i++) {
        float v = s2p[i];
        v += __shfl_xor_sync(0xffffffffu, v, 8);
        v += __shfl_xor_sync(0xffffffffu, v, 4);
        v += __shfl_xor_sync(0xffffffffu, v, 2);
        v += __shfl_xor_sync(0xffffffffu, v, 1);
        if (tx == 0) s2row[ty * 4 + i] = v;
    }
    __syncthreads();

    // Per-row dots: sumsq, e.v, e.chat[label]  (4 threads per row, 64 d each)
    {
        int r = t & 127, q = t >> 7;
        const float* er = Es + r * EP + q * 64;
        const float* vr = vsh + q * 64;
        const float* cr = g_chat + (size_t)labsh[r] * D + q * 64;
        float ss = 0.f, s1 = 0.f, sl = 0.f;
        #pragma unroll
        for (int m = 0; m < 16; m++) {
            float4 ev = *(const float4*)(er + m * 4);
            float4 vv = *(const float4*)(vr + m * 4);
            float4 cv = *(const float4*)(cr + m * 4);
            ss += ev.x * ev.x + ev.y * ev.y + ev.z * ev.z + ev.w * ev.w;
            s1 += ev.x * vv.x + ev.y * vv.y + ev.z * vv.z + ev.w * vv.w;
            sl += ev.x * cv.x + ev.y * cv.y + ev.z * cv.z + ev.w * cv.w;
        }
        redA[q * 128 + r] = ss;
        redB[q * 128 + r] = s1;
        redC[q * 128 + r] = sl;
    }
    __syncthreads();

    float li = 0.f;
    if (t < 128) {
        int r = t;
        float ss = redA[r] + redA[128 + r] + redA[256 + r] + redA[384 + r];
        float s1 = redB[r] + redB[128 + r] + redB[256 + r] + redB[384 + r];
        float sl = redC[r] + redC[128 + r] + redC[256 + r] + redC[384 + r];
        float rn = 1.f / fmaxf(sqrtf(ss), 1e-12f);
        float S1 = s1 * rn;
        float slab = sl * rn;
        float S2 = s2row[r] * rn * rn;
        float om = 1.f - slab;
        // loss_i = (1-slab)^2 * (1 - 1/(C-1)) + (C - 2*S1 + S2)/(C-1)
        li = om * om * (998.f / 999.f)
           + ((float)NC - 2.f * S1 + S2) * (1.f / 999.f);
    }
    // warp-reduce li (warps 0..3 carry data)
    #pragma unroll
    for (int off = 16; off; off >>= 1)
        li += __shfl_xor_sync(0xffffffffu, li, off);
    if ((t & 31) == 0 && t < 128) lsum[t >> 5] = li;
    __syncthreads();
    if (t == 0) atomicAdd(&g_loss, lsum[0] + lsum[1] + lsum[2] + lsum[3]);
}

// ---------------------------------------------------------------------------
__global__ void k_final(float* out) {
    if (threadIdx.x == 0) out[0] = g_loss * (1.f / (float)NROWS);
}

// ---------------------------------------------------------------------------
extern "C" void kernel_launch(void* const* d_in, const int* in_sizes, int n_in,
                              void* d_out, int out_size) {
    const float* emb = (const float*)d_in[0];
    const int* labels = (const int*)d_in[1];
    float* out = (float*)d_out;

    const int smem_bytes = (MROWS * EP + 256 * 64 + 256 + 128
                            + 3 * 512 + 128 + 4) * 4;
    cudaFuncSetAttribute(k_main, cudaFuncAttributeMaxDynamicSharedMemorySize,
                         smem_bytes);

    k_zero<<<1000, 256>>>();
    k_normacc<<<NROWS / 8, 256>>>(emb, labels);
    k_centers<<<NC, 256>>>();
    k_M<<<64, 256>>>();
    k_main<<<NROWS / MROWS, TPB, smem_bytes>>>(emb, labels);
    k_final<<<1, 32>>>(out);
}

// round 2
// speedup vs baseline: 1.2613x; 1.2613x over previous
#include <cuda_runtime.h>
#include <math.h>

#define NROWS 65536
#define D 256
#define NC 1000
#define NCP 1024         // padded class count (zero rows 1000..1023)
#define MROWS 128
#define EP 260           // Es pitch (floats), 260%4==0 for float4, breaks bank ties
#define TPB 512

// Scratch (device globals: no allocation allowed)
__device__ float g_sums[NC * D];
__device__ float g_counts[NC];
__device__ float g_chat[NCP * D];   // padded; rows >= NC stay zero
__device__ float g_v[D];
__device__ float g_M[D * D];
__device__ float g_loss;

// ---------------------------------------------------------------------------
__global__ void k_zero() {
    int i = blockIdx.x * 256 + threadIdx.x;   // grid 1024*256 = 262144
    if (i < NC * D) g_sums[i] = 0.f;
    if (i < NCP * D) g_chat[i] = 0.f;         // zero incl. padding rows
    if (i < D * D) g_M[i] = 0.f;
    if (i < NC) g_counts[i] = 0.f;
    if (i < D) g_v[i] = 0.f;
    if (i == 0) g_loss = 0.f;
}

// ---------------------------------------------------------------------------
// Normalize rows (warp per row) and accumulate per-class sums/counts.
__global__ void k_normacc(const float* __restrict__ emb,
                          const int* __restrict__ labels) {
    int warp = threadIdx.x >> 5, lane = threadIdx.x & 31;
    int row = blockIdx.x * 8 + warp;
    const float* e = emb + (size_t)row * D;

    float4 x0 = *(const float4*)(e + lane * 4);
    float4 x1 = *(const float4*)(e + 128 + lane * 4);
    float ss = x0.x * x0.x + x0.y * x0.y + x0.z * x0.z + x0.w * x0.w
             + x1.x * x1.x + x1.y * x1.y + x1.z * x1.z + x1.w * x1.w;
    #pragma unroll
    for (int off = 16; off; off >>= 1)
        ss += __shfl_xor_sync(0xffffffffu, ss, off);

    float rn = 1.f / fmaxf(sqrtf(ss), 1e-12f);
    int lab = labels[row];
    float* dst = g_sums + (size_t)lab * D;
    atomicAdd(dst + lane * 4 + 0,       x0.x * rn);
    atomicAdd(dst + lane * 4 + 1,       x0.y * rn);
    atomicAdd(dst + lane * 4 + 2,       x0.z * rn);
    atomicAdd(dst + lane * 4 + 3,       x0.w * rn);
    atomicAdd(dst + 128 + lane * 4 + 0, x1.x * rn);
    atomicAdd(dst + 128 + lane * 4 + 1, x1.y * rn);
    atomicAdd(dst + 128 + lane * 4 + 2, x1.z * rn);
    atomicAdd(dst + 128 + lane * 4 + 3, x1.w * rn);
    if (lane == 0) atomicAdd(&g_counts[lab], 1.f);
}

// ---------------------------------------------------------------------------
// Per-class: center = sum/max(count,1); chat = center/max(||center||,1e-8); v += chat
__global__ void k_centers() {
    int c = blockIdx.x, t = threadIdx.x;
    float cnt = g_counts[c];
    float center = g_sums[(size_t)c * D + t] / fmaxf(cnt, 1.f);

    float ss = center * center;
    #pragma unroll
    for (int off = 16; off; off >>= 1)
        ss += __shfl_xor_sync(0xffffffffu, ss, off);
    __shared__ float wsum[8];
    __shared__ float denom_s;
    if ((t & 31) == 0) wsum[t >> 5] = ss;
    __syncthreads();
    if (t == 0) {
        float tot = 0.f;
        #pragma unroll
        for (int w = 0; w < 8; w++) tot += wsum[w];
        denom_s = fmaxf(sqrtf(tot), 1e-8f);
    }
    __syncthreads();
    float ch = center / denom_s;
    g_chat[(size_t)c * D + t] = ch;
    atomicAdd(&g_v[t], ch);
}

// ---------------------------------------------------------------------------
// M = Chat^T Chat (256x256, K=1024 padded). Tiled K-split GEMM:
// grid (4,4,16): 64x64 output tile, 64 K-rows per z-slice, atomicAdd epilogue.
__global__ __launch_bounds__(256) void k_M() {
    __shared__ float As[16][64];
    __shared__ float Bs[16][64];
    int t = threadIdx.x;
    int tx = t & 15, ty = t >> 4;            // 16x16 thread grid
    int cb = blockIdx.x * 64;                 // output cols
    int rb = blockIdx.y * 64;                 // output rows
    int k0 = blockIdx.z * 64;                 // K slice base

    float acc[4][4] = {};
    #pragma unroll 1
    for (int kc = 0; kc < 4; kc++) {          // 4 chunks of KT=16
        __syncthreads();
        // load 16x64 tiles of Chat for row-range and col-range
        {
            int idx = t;                       // 0..255 float4 slots (16*64/4=256)
            int kk = idx >> 4, c4 = (idx & 15) << 2;
            const float* src = g_chat + (size_t)(k0 + kc * 16 + kk) * D;
            *(float4*)&As[kk][c4] = *(const float4*)(src + rb + c4);
            *(float4*)&Bs[kk][c4] = *(const float4*)(src + cb + c4);
        }
        __syncthreads();
        #pragma unroll
        for (int kk = 0; kk < 16; kk++) {
            float a[4], b[4];
            *(float4*)a = *(float4*)&As[kk][ty * 4];
            *(float4*)b = *(float4*)&Bs[kk][tx * 4];
            #pragma unroll
            for (int i = 0; i < 4; i++)
                #pragma unroll
                for (int j = 0; j < 4; j++)
                    acc[i][j] += a[i] * b[j];
        }
    }
    #pragma unroll
    for (int i = 0; i < 4; i++)
        #pragma unroll
        for (int j = 0; j < 4; j++)
            atomicAdd(&g_M[(size_t)(rb + ty * 4 + i) * D + cb + tx * 4 + j],
                      acc[i][j]);
}

// ---------------------------------------------------------------------------
// Main fused kernel: per 128-row tile compute T = E*M (4 x 64-col chunks),
// fold into S2 = e^T M e, plus S1 = e.v, slab = e.chat[label], row norm, loss.
__global__ __launch_bounds__(TPB, 1)
void k_main(const float* __restrict__ emb, const int* __restrict__ labels) {
    extern __shared__ float sh[];
    float* Es    = sh;                    // MROWS*EP   = 33280
    float* Ms    = Es + MROWS * EP;       // 256*64     = 16384
    float* vsh   = Ms + 256 * 64;         // 256
    float* s2row = vsh + 256;             // 128
    float* redA  = s2row + 128;           // 512
    float* redB  = redA + 512;            // 512
    float* redC  = redB + 512;            // 512
    int*   labsh = (int*)(redC + 512);    // 128
    float* lsum  = (float*)(labsh + 128); // 4

    int t = threadIdx.x;
    int row0 = blockIdx.x * MROWS;

    // Load E tile [128 x 256] (row-major, pitch EP)
    #pragma unroll
    for (int i = 0; i < 16; i++) {
        int idx = t + i * TPB;            // float4 index, 0..8191
        int r = idx >> 6, c4 = (idx & 63) << 2;
        float4 x = *(const float4*)(emb + (size_t)(row0 + r) * D + c4);
        *(float4*)(Es + r * EP + c4) = x;
    }
    if (t < 256) vsh[t] = g_v[t];
    if (t < 128) labsh[t] = labels[row0 + t];

    int tx = t & 15, ty = t >> 4;
    float s2p[4] = {0.f, 0.f, 0.f, 0.f};

    for (int dc = 0; dc < 4; dc++) {
        __syncthreads();
        // Load M chunk [256 x 64]
        #pragma unroll
        for (int i = 0; i < 8; i++) {
            int idx = t + i * TPB;        // float4 index, 0..4095
            int k = idx >> 4, c4 = (idx & 15) << 2;
            *(float4*)(Ms + k * 64 + c4) =
                *(const float4*)(g_M + (size_t)k * D + dc * 64 + c4);
        }
        __syncthreads();

        float acc[4][4] = {};
        const float* arow = Es + (ty * 4) * EP;
        #pragma unroll 4
        for (int k = 0; k < 256; k++) {
            float4 b = *(const float4*)(Ms + k * 64 + tx * 4);
            float a0 = arow[k];
            float a1 = arow[EP + k];
            float a2 = arow[2 * EP + k];
            float a3 = arow[3 * EP + k];
            acc[0][0] += a0 * b.x; acc[0][1] += a0 * b.y; acc[0][2] += a0 * b.z; acc[0][3] += a0 * b.w;
            acc[1][0] += a1 * b.x; acc[1][1] += a1 * b.y; acc[1][2] += a1 * b.z; acc[1][3] += a1 * b.w;
            acc[2][0] += a2 * b.x; acc[2][1] += a2 * b.y; acc[2][2] += a2 * b.z; acc[2][3] += a2 * b.w;
            acc[3][0] += a3 * b.x; acc[3][1] += a3 * b.y; acc[3][2] += a3 * b.z; acc[3][3] += a3 * b.w;
        }
        // Fold tile into S2 partials: t[r][d] * e[r][d]
        #pragma unroll
        for (int i = 0; i < 4; i++) {
            float4 e4 = *(const float4*)(Es + (ty * 4 + i) * EP + dc * 64 + tx * 4);
            s2p[i] += acc[i][0] * e4.x + acc[i][1] * e4.y
                    + acc[i][2] * e4.z + acc[i][3] * e4.w;
        }
    }

    // Reduce S2 partials across the 16 tx lanes (xor<16 stays in same ty group)
    #pragma unroll
    for (int i = 0; i < 4; i++) {
        float v = s2p[i];
        v += __shfl_xor_sync(0xffffffffu, v, 8);
        v += __shfl_xor_sync(0xffffffffu, v, 4);
        v += __shfl_xor_sync(0xffffffffu, v, 2);
        v += __shfl_xor_sync(0xffffffffu, v, 1);
        if (tx == 0) s2row[ty * 4 + i] = v;
    }
    __syncthreads();

    // Per-row dots: sumsq, e.v, e.chat[label]  (4 threads per row, 64 d each)
    {
        int r = t & 127, q = t >> 7;
        const float* er = Es + r * EP + q * 64;
        const float* vr = vsh + q * 64;
        const float* cr = g_chat + (size_t)labsh[r] * D + q * 64;
        float ss = 0.f, s1 = 0.f, sl = 0.f;
        #pragma unroll
        for (int m = 0; m < 16; m++) {
            float4 ev = *(const float4*)(er + m * 4);
            float4 vv = *(const float4*)(vr + m * 4);
            float4 cv = *(const float4*)(cr + m * 4);
            ss += ev.x * ev.x + ev.y * ev.y + ev.z * ev.z + ev.w * ev.w;
            s1 += ev.x * vv.x + ev.y * vv.y + ev.z * vv.z + ev.w * vv.w;
            sl += ev.x * cv.x + ev.y * cv.y + ev.z * cv.z + ev.w * cv.w;
        }
        redA[q * 128 + r] = ss;
        redB[q * 128 + r] = s1;
        redC[q * 128 + r] = sl;
    }
    __syncthreads();

    float li = 0.f;
    if (t < 128) {
        int r = t;
        float ss = redA[r] + redA[128 + r] + redA[256 + r] + redA[384 + r];
        float s1 = redB[r] + redB[128 + r] + redB[256 + r] + redB[384 + r];
        float sl = redC[r] + redC[128 + r] + redC[256 + r] + redC[384 + r];
        float rn = 1.f / fmaxf(sqrtf(ss), 1e-12f);
        float S1 = s1 * rn;
        float slab = sl * rn;
        float S2 = s2row[r] * rn * rn;
        float om = 1.f - slab;
        // loss_i = (1-slab)^2 * (1 - 1/(C-1)) + (C - 2*S1 + S2)/(C-1)
        li = om * om * (998.f / 999.f)
           + ((float)NC - 2.f * S1 + S2) * (1.f / 999.f);
    }
    // warp-reduce li (warps 0..3 carry data)
    #pragma unroll
    for (int off = 16; off; off >>= 1)
        li += __shfl_xor_sync(0xffffffffu, li, off);
    if ((t & 31) == 0 && t < 128) lsum[t >> 5] = li;
    __syncthreads();
    if (t == 0) atomicAdd(&g_loss, lsum[0] + lsum[1] + lsum[2] + lsum[3]);
}

// ---------------------------------------------------------------------------
__global__ void k_final(float* out) {
    if (threadIdx.x == 0) out[0] = g_loss * (1.f / (float)NROWS);
}

// ---------------------------------------------------------------------------
extern "C" void kernel_launch(void* const* d_in, const int* in_sizes, int n_in,
                              void* d_out, int out_size) {
    const float* emb = (const float*)d_in[0];
    const int* labels = (const int*)d_in[1];
    float* out = (float*)d_out;

    const int smem_bytes = (MROWS * EP + 256 * 64 + 256 + 128
                            + 3 * 512 + 128 + 4) * 4;
    cudaFuncSetAttribute(k_main, cudaFuncAttributeMaxDynamicSharedMemorySize,
                         smem_bytes);

    k_zero<<<1024, 256>>>();
    k_normacc<<<NROWS / 8, 256>>>(emb, labels);
    k_centers<<<NC, 256>>>();
    k_M<<<dim3(4, 4, 16), 256>>>();
    k_main<<<NROWS / MROWS, TPB, smem_bytes>>>(emb, labels);
    k_final<<<1, 32>>>(out);
}

// round 4
// speedup vs baseline: 2.7743x; 2.1995x over previous
#include <cuda_runtime.h>
#include <math.h>
#include <stdint.h>

#define NROWS 65536
#define D 256
#define NC 1000
#define NCP 1024
#define MROWS 128
#define TPB 256
#define EP 260      // Es pitch (floats): 260%32=4 -> conflict-free A frags
#define MP 72       // Ms pitch (floats): 72%32=8  -> conflict-free B frags

// ---------------- device scratch ----------------
__device__ float g_sums[NC * D];
__device__ float g_counts[NC];
__device__ float g_chat[NCP * D];
__device__ float g_v[D];
__device__ float g_M[D * D];
__device__ float g_loss;

__device__ __forceinline__ float to_tf32(float x) {
    asm("cvt.rna.tf32.f32 %0, %1;" : "=f"(x) : "f"(x));
    return x;
}

// ---------------------------------------------------------------------------
__global__ void k_zero() {
    int i = blockIdx.x * 256 + threadIdx.x;
    if (i < NC * D) g_sums[i] = 0.f;
    if (i < NCP * D) g_chat[i] = 0.f;
    if (i < D * D) g_M[i] = 0.f;
    if (i < NC) g_counts[i] = 0.f;
    if (i < D) g_v[i] = 0.f;
    if (i == 0) g_loss = 0.f;
}

// ---------------------------------------------------------------------------
__global__ void k_normacc(const float* __restrict__ emb,
                          const int* __restrict__ labels) {
    int warp = threadIdx.x >> 5, lane = threadIdx.x & 31;
    int row = blockIdx.x * 8 + warp;
    const float* e = emb + (size_t)row * D;

    float4 x0 = *(const float4*)(e + lane * 4);
    float4 x1 = *(const float4*)(e + 128 + lane * 4);
    float ss = x0.x * x0.x + x0.y * x0.y + x0.z * x0.z + x0.w * x0.w
             + x1.x * x1.x + x1.y * x1.y + x1.z * x1.z + x1.w * x1.w;
    #pragma unroll
    for (int off = 16; off; off >>= 1)
        ss += __shfl_xor_sync(0xffffffffu, ss, off);

    float rn = 1.f / fmaxf(sqrtf(ss), 1e-12f);
    int lab = labels[row];
    float* dst = g_sums + (size_t)lab * D;
    atomicAdd(dst + lane * 4 + 0,       x0.x * rn);
    atomicAdd(dst + lane * 4 + 1,       x0.y * rn);
    atomicAdd(dst + lane * 4 + 2,       x0.z * rn);
    atomicAdd(dst + lane * 4 + 3,       x0.w * rn);
    atomicAdd(dst + 128 + lane * 4 + 0, x1.x * rn);
    atomicAdd(dst + 128 + lane * 4 + 1, x1.y * rn);
    atomicAdd(dst + 128 + lane * 4 + 2, x1.z * rn);
    atomicAdd(dst + 128 + lane * 4 + 3, x1.w * rn);
    if (lane == 0) atomicAdd(&g_counts[lab], 1.f);
}

// ---------------------------------------------------------------------------
__global__ void k_centers() {
    int c = blockIdx.x, t = threadIdx.x;
    float cnt = g_counts[c];
    float center = g_sums[(size_t)c * D + t] / fmaxf(cnt, 1.f);

    float ss = center * center;
    #pragma unroll
    for (int off = 16; off; off >>= 1)
        ss += __shfl_xor_sync(0xffffffffu, ss, off);
    __shared__ float wsum[8];
    __shared__ float denom_s;
    if ((t & 31) == 0) wsum[t >> 5] = ss;
    __syncthreads();
    if (t == 0) {
        float tot = 0.f;
        #pragma unroll
        for (int w = 0; w < 8; w++) tot += wsum[w];
        denom_s = fmaxf(sqrtf(tot), 1e-8f);
    }
    __syncthreads();
    float ch = center / denom_s;
    g_chat[(size_t)c * D + t] = ch;
    atomicAdd(&g_v[t], ch);
}

// ---------------------------------------------------------------------------
// M = Chat^T Chat (K=1024 padded). Tiled K-split GEMM, atomicAdd epilogue.
__global__ __launch_bounds__(256) void k_M() {
    __shared__ float As[16][64];
    __shared__ float Bs[16][64];
    int t = threadIdx.x;
    int tx = t & 15, ty = t >> 4;
    int cb = blockIdx.x * 64;
    int rb = blockIdx.y * 64;
    int k0 = blockIdx.z * 64;

    float acc[4][4] = {};
    #pragma unroll 1
    for (int kc = 0; kc < 4; kc++) {
        __syncthreads();
        {
            int idx = t;
            int kk = idx >> 4, c4 = (idx & 15) << 2;
            const float* src = g_chat + (size_t)(k0 + kc * 16 + kk) * D;
            *(float4*)&As[kk][c4] = *(const float4*)(src + rb + c4);
            *(float4*)&Bs[kk][c4] = *(const float4*)(src + cb + c4);
        }
        __syncthreads();
        #pragma unroll
        for (int kk = 0; kk < 16; kk++) {
            float a[4], b[4];
            *(float4*)a = *(float4*)&As[kk][ty * 4];
            *(float4*)b = *(float4*)&Bs[kk][tx * 4];
            #pragma unroll
            for (int i = 0; i < 4; i++)
                #pragma unroll
                for (int j = 0; j < 4; j++)
                    acc[i][j] += a[i] * b[j];
        }
    }
    #pragma unroll
    for (int i = 0; i < 4; i++)
        #pragma unroll
        for (int j = 0; j < 4; j++)
            atomicAdd(&g_M[(size_t)(rb + ty * 4 + i) * D + cb + tx * 4 + j],
                      acc[i][j]);
}

// ---------------------------------------------------------------------------
// Main fused kernel. T = E*M via mma.sync tf32 (tensor pipe), S2 folded from
// register accumulators; then per-row dots + loss.
__global__ __launch_bounds__(TPB, 1)
void k_main(const float* __restrict__ emb, const int* __restrict__ labels) {
    extern __shared__ float sh[];
    float* Es    = sh;                       // 128*EP = 33280 floats
    float* Ms    = Es + MROWS * EP;          // 256*MP = 18432 floats
    float* vsh   = Ms + 256 * MP;            // 256
    float* s2row = vsh + 256;                // 128
    float* redA  = s2row + 128;              // 256
    float* redB  = redA + 256;               // 256
    float* redC  = redB + 256;               // 256
    int*   labsh = (int*)(redC + 256);       // 128
    float* lsum  = (float*)(labsh + 128);    // 8

    int t = threadIdx.x;
    int w = t >> 5, lane = t & 31;
    int g = lane >> 2, j = lane & 3;         // groupID, threadID_in_group
    int rb = (w & 3) * 32;                   // warp row base (0..96)
    int nb = (w >> 2) * 32;                  // warp col base within 64-chunk
    int row0 = blockIdx.x * MROWS;

    // Load E tile [128 x 256] raw f32
    #pragma unroll
    for (int i = 0; i < 32; i++) {
        int idx = t + i * TPB;               // float4 slot 0..8191
        int r = idx >> 6, c = (idx & 63) << 2;
        float4 x = *(const float4*)(emb + (size_t)(row0 + r) * D + c);
        *(float4*)(Es + r * EP + c) = x;
    }
    if (t < 128) labsh[t] = labels[row0 + t];
    if (t < 128) s2row[t] = 0.f;
    vsh[t] = g_v[t];

    float s2p[4] = {0.f, 0.f, 0.f, 0.f};     // rows rb+g, rb+g+8, rb+16+g, rb+24+g

    #pragma unroll 1
    for (int dc = 0; dc < 4; dc++) {
        __syncthreads();
        // Load M chunk [256 k x 64 n] -> Ms (pitch MP), tf32-rounded
        #pragma unroll
        for (int i = 0; i < 16; i++) {
            int idx = t + i * TPB;           // float4 slot 0..4095
            int k = idx >> 4, c = (idx & 15) << 2;
            float4 x = *(const float4*)(g_M + (size_t)k * D + dc * 64 + c);
            x.x = to_tf32(x.x); x.y = to_tf32(x.y);
            x.z = to_tf32(x.z); x.w = to_tf32(x.w);
            *(float4*)(Ms + k * MP + c) = x;
        }
        __syncthreads();

        float acc[2][4][4] = {};
        #pragma unroll 2
        for (int ks = 0; ks < 32; ks++) {
            int k = ks * 8;
            uint32_t a[2][4];
            #pragma unroll
            for (int mt = 0; mt < 2; mt++) {
                const float* ar = Es + (rb + mt * 16 + g) * EP + k + j;
                a[mt][0] = __float_as_uint(ar[0]);
                a[mt][1] = __float_as_uint(ar[8 * EP]);
                a[mt][2] = __float_as_uint(ar[4]);
                a[mt][3] = __float_as_uint(ar[8 * EP + 4]);
            }
            #pragma unroll
            for (int nt = 0; nt < 4; nt++) {
                uint32_t b0 = __float_as_uint(Ms[(k + j) * MP + nb + nt * 8 + g]);
                uint32_t b1 = __float_as_uint(Ms[(k + j + 4) * MP + nb + nt * 8 + g]);
                #pragma unroll
                for (int mt = 0; mt < 2; mt++) {
                    asm volatile(
                        "mma.sync.aligned.m16n8k8.row.col.f32.tf32.tf32.f32 "
                        "{%0,%1,%2,%3}, {%4,%5,%6,%7}, {%8,%9}, {%0,%1,%2,%3};"
                        : "+f"(acc[mt][nt][0]), "+f"(acc[mt][nt][1]),
                          "+f"(acc[mt][nt][2]), "+f"(acc[mt][nt][3])
                        : "r"(a[mt][0]), "r"(a[mt][1]), "r"(a[mt][2]), "r"(a[mt][3]),
                          "r"(b0), "r"(b1));
                }
            }
        }
        // Fold T-chunk into s2 partials: s2p += T[r][c]*E[r][c]
        #pragma unroll
        for (int mt = 0; mt < 2; mt++) {
            #pragma unroll
            for (int nt = 0; nt < 4; nt++) {
                int c = dc * 64 + nb + nt * 8 + 2 * j;
                int r0 = rb + mt * 16 + g;
                float2 e0 = *(const float2*)(Es + r0 * EP + c);
                float2 e1 = *(const float2*)(Es + (r0 + 8) * EP + c);
                s2p[mt * 2 + 0] += acc[mt][nt][0] * e0.x + acc[mt][nt][1] * e0.y;
                s2p[mt * 2 + 1] += acc[mt][nt][2] * e1.x + acc[mt][nt][3] * e1.y;
            }
        }
    }

    // Reduce s2 partials across the 4 lanes of each group (same rows)
    #pragma unroll
    for (int i = 0; i < 4; i++) {
        float v = s2p[i];
        v += __shfl_xor_sync(0xffffffffu, v, 1);
        v += __shfl_xor_sync(0xffffffffu, v, 2);
        s2p[i] = v;
    }
    if (j == 0) {
        atomicAdd(&s2row[rb + g],      s2p[0]);
        atomicAdd(&s2row[rb + g + 8],  s2p[1]);
        atomicAdd(&s2row[rb + 16 + g], s2p[2]);
        atomicAdd(&s2row[rb + 24 + g], s2p[3]);
    }

    // Per-row dots: ss, e.v, e.chat[label]  (2 threads per row, 128 cols each)
    {
        int r = t & 127, q = t >> 7;
        const float* er = Es + r * EP + q * 128;
        const float* vr = vsh + q * 128;
        const float* cr = g_chat + (size_t)labsh[r] * D + q * 128;
        float ss = 0.f, s1 = 0.f, sl = 0.f;
        #pragma unroll
        for (int m = 0; m < 32; m++) {
            float4 ev = *(const float4*)(er + m * 4);
            float4 vv = *(const float4*)(vr + m * 4);
            float4 cv = *(const float4*)(cr + m * 4);
            ss += ev.x * ev.x + ev.y * ev.y + ev.z * ev.z + ev.w * ev.w;
            s1 += ev.x * vv.x + ev.y * vv.y + ev.z * vv.z + ev.w * vv.w;
            sl += ev.x * cv.x + ev.y * cv.y + ev.z * cv.z + ev.w * cv.w;
        }
        redA[q * 128 + r] = ss;
        redB[q * 128 + r] = s1;
        redC[q * 128 + r] = sl;
    }
    __syncthreads();

    float li = 0.f;
    if (t < 128) {
        int r = t;
        float ss = redA[r] + redA[128 + r];
        float s1 = redB[r] + redB[128 + r];
        float sl = redC[r] + redC[128 + r];
        float rn = 1.f / fmaxf(sqrtf(ss), 1e-12f);
        float S1 = s1 * rn;
        float slab = sl * rn;
        float S2 = s2row[r] * rn * rn;
        float om = 1.f - slab;
        li = om * om * (998.f / 999.f)
           + ((float)NC - 2.f * S1 + S2) * (1.f / 999.f);
    }
    #pragma unroll
    for (int off = 16; off; off >>= 1)
        li += __shfl_xor_sync(0xffffffffu, li, off);
    if ((t & 31) == 0 && t < 128) lsum[t >> 5] = li;
    __syncthreads();
    if (t == 0) atomicAdd(&g_loss, lsum[0] + lsum[1] + lsum[2] + lsum[3]);
}

// ---------------------------------------------------------------------------
__global__ void k_final(float* out) {
    if (threadIdx.x == 0) out[0] = g_loss * (1.f / (float)NROWS);
}

// ---------------------------------------------------------------------------
extern "C" void kernel_launch(void* const* d_in, const int* in_sizes, int n_in,
                              void* d_out, int out_size) {
    const float* emb = (const float*)d_in[0];
    const int* labels = (const int*)d_in[1];
    float* out = (float*)d_out;

    const int smem_bytes = (MROWS * EP + 256 * MP + 256 + 128
                            + 3 * 256 + 128 + 8) * 4;
    cudaFuncSetAttribute(k_main, cudaFuncAttributeMaxDynamicSharedMemorySize,
                         smem_bytes);

    k_zero<<<1024, 256>>>();
    k_normacc<<<NROWS / 8, 256>>>(emb, labels);
    k_centers<<<NC, 256>>>();
    k_M<<<dim3(4, 4, 16), 256>>>();
    k_main<<<NROWS / MROWS, TPB, smem_bytes>>>(emb, labels);
    k_final<<<1, 32>>>(out);
}

// round 5
// speedup vs baseline: 3.2505x; 1.1716x over previous
#include <cuda_runtime.h>
#include <math.h>
#include <stdint.h>

#define NROWS 65536
#define D 256
#define NC 1000
#define NCP 1024
#define MROWS 128
#define TPB 256
#define EP 260      // Es pitch (floats): 260%32=4 -> conflict-free A frags
#define MP 72       // Ms pitch (floats): 72%32=8  -> conflict-free B frags
#define NREP 4      // g_sums replicas

// ---------------- device scratch ----------------
__device__ float g_sums[NREP * NC * D];
__device__ float g_counts[NREP * NC];
__device__ float g_chat[NCP * D];
__device__ float g_v[D];
__device__ float g_M[D * D];
__device__ float g_loss;

__device__ __forceinline__ float to_tf32(float x) {
    asm("cvt.rna.tf32.f32 %0, %1;" : "=f"(x) : "f"(x));
    return x;
}
__device__ __forceinline__ void red_v4(float* p, float a, float b, float c, float d) {
    asm volatile("red.global.add.v4.f32 [%0], {%1,%2,%3,%4};"
                 :: "l"(p), "f"(a), "f"(b), "f"(c), "f"(d) : "memory");
}

// ---------------------------------------------------------------------------
__global__ void k_zero() {
    int i = blockIdx.x * 256 + threadIdx.x;   // grid 4096*256
    if (i < NREP * NC * D) g_sums[i] = 0.f;
    if (i < NCP * D) g_chat[i] = 0.f;
    if (i < D * D) g_M[i] = 0.f;
    if (i < NREP * NC) g_counts[i] = 0.f;
    if (i < D) g_v[i] = 0.f;
    if (i == 0) g_loss = 0.f;
}

// ---------------------------------------------------------------------------
// Normalize rows (warp per row); vector-red into replicated class sums.
__global__ void k_normacc(const float* __restrict__ emb,
                          const int* __restrict__ labels) {
    int warp = threadIdx.x >> 5, lane = threadIdx.x & 31;
    int row = blockIdx.x * 8 + warp;
    const float* e = emb + (size_t)row * D;

    float4 x0 = *(const float4*)(e + lane * 4);
    float4 x1 = *(const float4*)(e + 128 + lane * 4);
    float ss = x0.x * x0.x + x0.y * x0.y + x0.z * x0.z + x0.w * x0.w
             + x1.x * x1.x + x1.y * x1.y + x1.z * x1.z + x1.w * x1.w;
    #pragma unroll
    for (int off = 16; off; off >>= 1)
        ss += __shfl_xor_sync(0xffffffffu, ss, off);

    float rn = 1.f / fmaxf(sqrtf(ss), 1e-12f);
    int lab = labels[row];
    int rep = (row >> 3) & (NREP - 1);
    float* dst = g_sums + ((size_t)rep * NC + lab) * D;
    red_v4(dst + lane * 4,       x0.x * rn, x0.y * rn, x0.z * rn, x0.w * rn);
    red_v4(dst + 128 + lane * 4, x1.x * rn, x1.y * rn, x1.z * rn, x1.w * rn);
    if (lane == 0) atomicAdd(&g_counts[rep * NC + lab], 1.f);
}

// ---------------------------------------------------------------------------
// Per-class: fold replicas; center = sum/max(count,1); chat = center/||center||
__global__ void k_centers() {
    int c = blockIdx.x, t = threadIdx.x;
    float cnt = g_counts[c] + g_counts[NC + c]
              + g_counts[2 * NC + c] + g_counts[3 * NC + c];
    float s = g_sums[(size_t)c * D + t]
            + g_sums[(size_t)(NC + c) * D + t]
            + g_sums[(size_t)(2 * NC + c) * D + t]
            + g_sums[(size_t)(3 * NC + c) * D + t];
    float center = s / fmaxf(cnt, 1.f);

    float ss = center * center;
    #pragma unroll
    for (int off = 16; off; off >>= 1)
        ss += __shfl_xor_sync(0xffffffffu, ss, off);
    __shared__ float wsum[8];
    __shared__ float denom_s;
    if ((t & 31) == 0) wsum[t >> 5] = ss;
    __syncthreads();
    if (t == 0) {
        float tot = 0.f;
        #pragma unroll
        for (int w = 0; w < 8; w++) tot += wsum[w];
        denom_s = fmaxf(sqrtf(tot), 1e-8f);
    }
    __syncthreads();
    float ch = center / denom_s;
    g_chat[(size_t)c * D + t] = ch;
    atomicAdd(&g_v[t], ch);
}

// ---------------------------------------------------------------------------
// M = Chat^T Chat (K=1024 padded). Tiled K-split GEMM, atomicAdd epilogue.
__global__ __launch_bounds__(256) void k_M() {
    __shared__ float As[16][64];
    __shared__ float Bs[16][64];
    int t = threadIdx.x;
    int tx = t & 15, ty = t >> 4;
    int cb = blockIdx.x * 64;
    int rb = blockIdx.y * 64;
    int k0 = blockIdx.z * 64;

    float acc[4][4] = {};
    #pragma unroll 1
    for (int kc = 0; kc < 4; kc++) {
        __syncthreads();
        {
            int idx = t;
            int kk = idx >> 4, c4 = (idx & 15) << 2;
            const float* src = g_chat + (size_t)(k0 + kc * 16 + kk) * D;
            *(float4*)&As[kk][c4] = *(const float4*)(src + rb + c4);
            *(float4*)&Bs[kk][c4] = *(const float4*)(src + cb + c4);
        }
        __syncthreads();
        #pragma unroll
        for (int kk = 0; kk < 16; kk++) {
            float a[4], b[4];
            *(float4*)a = *(float4*)&As[kk][ty * 4];
            *(float4*)b = *(float4*)&Bs[kk][tx * 4];
            #pragma unroll
            for (int i = 0; i < 4; i++)
                #pragma unroll
                for (int j = 0; j < 4; j++)
                    acc[i][j] += a[i] * b[j];
        }
    }
    #pragma unroll
    for (int i = 0; i < 4; i++)
        #pragma unroll
        for (int j = 0; j < 4; j++)
            atomicAdd(&g_M[(size_t)(rb + ty * 4 + i) * D + cb + tx * 4 + j],
                      acc[i][j]);
}

// ---------------------------------------------------------------------------
// Main fused kernel. T = E*M via mma.sync tf32 (tensor pipe), S2 folded from
// register accumulators; then per-row dots + loss.
__global__ __launch_bounds__(TPB, 1)
void k_main(const float* __restrict__ emb, const int* __restrict__ labels) {
    extern __shared__ float sh[];
    float* Es    = sh;                       // 128*EP = 33280 floats
    float* Ms    = Es + MROWS * EP;          // 256*MP = 18432 floats
    float* vsh   = Ms + 256 * MP;            // 256
    float* s2row = vsh + 256;                // 128
    float* redA  = s2row + 128;              // 256
    float* redB  = redA + 256;               // 256
    float* redC  = redB + 256;               // 256
    int*   labsh = (int*)(redC + 256);       // 128
    float* lsum  = (float*)(labsh + 128);    // 8

    int t = threadIdx.x;
    int w = t >> 5, lane = t & 31;
    int g = lane >> 2, j = lane & 3;         // groupID, threadID_in_group
    int rb = (w & 3) * 32;                   // warp row base (0..96)
    int nb = (w >> 2) * 32;                  // warp col base within 64-chunk
    int row0 = blockIdx.x * MROWS;

    // Load E tile [128 x 256] raw f32
    #pragma unroll
    for (int i = 0; i < 32; i++) {
        int idx = t + i * TPB;               // float4 slot 0..8191
        int r = idx >> 6, c = (idx & 63) << 2;
        float4 x = *(const float4*)(emb + (size_t)(row0 + r) * D + c);
        *(float4*)(Es + r * EP + c) = x;
    }
    if (t < 128) labsh[t] = labels[row0 + t];
    if (t < 128) s2row[t] = 0.f;
    vsh[t] = g_v[t];

    float s2p[4] = {0.f, 0.f, 0.f, 0.f};     // rows rb+g, rb+g+8, rb+16+g, rb+24+g

    #pragma unroll 1
    for (int dc = 0; dc < 4; dc++) {
        __syncthreads();
        // Load M chunk [256 k x 64 n] -> Ms (pitch MP), tf32-rounded
        #pragma unroll
        for (int i = 0; i < 16; i++) {
            int idx = t + i * TPB;           // float4 slot 0..4095
            int k = idx >> 4, c = (idx & 15) << 2;
            float4 x = *(const float4*)(g_M + (size_t)k * D + dc * 64 + c);
            x.x = to_tf32(x.x); x.y = to_tf32(x.y);
            x.z = to_tf32(x.z); x.w = to_tf32(x.w);
            *(float4*)(Ms + k * MP + c) = x;
        }
        __syncthreads();

        float acc[2][4][4] = {};
        #pragma unroll 2
        for (int ks = 0; ks < 32; ks++) {
            int k = ks * 8;
            uint32_t a[2][4];
            #pragma unroll
            for (int mt = 0; mt < 2; mt++) {
                const float* ar = Es + (rb + mt * 16 + g) * EP + k + j;
                a[mt][0] = __float_as_uint(ar[0]);
                a[mt][1] = __float_as_uint(ar[8 * EP]);
                a[mt][2] = __float_as_uint(ar[4]);
                a[mt][3] = __float_as_uint(ar[8 * EP + 4]);
            }
            #pragma unroll
            for (int nt = 0; nt < 4; nt++) {
                uint32_t b0 = __float_as_uint(Ms[(k + j) * MP + nb + nt * 8 + g]);
                uint32_t b1 = __float_as_uint(Ms[(k + j + 4) * MP + nb + nt * 8 + g]);
                #pragma unroll
                for (int mt = 0; mt < 2; mt++) {
                    asm volatile(
                        "mma.sync.aligned.m16n8k8.row.col.f32.tf32.tf32.f32 "
                        "{%0,%1,%2,%3}, {%4,%5,%6,%7}, {%8,%9}, {%0,%1,%2,%3};"
                        : "+f"(acc[mt][nt][0]), "+f"(acc[mt][nt][1]),
                          "+f"(acc[mt][nt][2]), "+f"(acc[mt][nt][3])
                        : "r"(a[mt][0]), "r"(a[mt][1]), "r"(a[mt][2]), "r"(a[mt][3]),
                          "r"(b0), "r"(b1));
                }
            }
        }
        // Fold T-chunk into s2 partials: s2p += T[r][c]*E[r][c]
        #pragma unroll
        for (int mt = 0; mt < 2; mt++) {
            #pragma unroll
            for (int nt = 0; nt < 4; nt++) {
                int c = dc * 64 + nb + nt * 8 + 2 * j;
                int r0 = rb + mt * 16 + g;
                float2 e0 = *(const float2*)(Es + r0 * EP + c);
                float2 e1 = *(const float2*)(Es + (r0 + 8) * EP + c);
                s2p[mt * 2 + 0] += acc[mt][nt][0] * e0.x + acc[mt][nt][1] * e0.y;
                s2p[mt * 2 + 1] += acc[mt][nt][2] * e1.x + acc[mt][nt][3] * e1.y;
            }
        }
    }

    // Reduce s2 partials across the 4 lanes of each group (same rows)
    #pragma unroll
    for (int i = 0; i < 4; i++) {
        float v = s2p[i];
        v += __shfl_xor_sync(0xffffffffu, v, 1);
        v += __shfl_xor_sync(0xffffffffu, v, 2);
        s2p[i] = v;
    }
    if (j == 0) {
        atomicAdd(&s2row[rb + g],      s2p[0]);
        atomicAdd(&s2row[rb + g + 8],  s2p[1]);
        atomicAdd(&s2row[rb + 16 + g], s2p[2]);
        atomicAdd(&s2row[rb + 24 + g], s2p[3]);
    }

    // Per-row dots: ss, e.v, e.chat[label]  (2 threads per row, 128 cols each)
    {
        int r = t & 127, q = t >> 7;
        const float* er = Es + r * EP + q * 128;
        const float* vr = vsh + q * 128;
        const float* cr = g_chat + (size_t)labsh[r] * D + q * 128;
        float ss = 0.f, s1 = 0.f, sl = 0.f;
        #pragma unroll
        for (int m = 0; m < 32; m++) {
            float4 ev = *(const float4*)(er + m * 4);
            float4 vv = *(const float4*)(vr + m * 4);
            float4 cv = *(const float4*)(cr + m * 4);
            ss += ev.x * ev.x + ev.y * ev.y + ev.z * ev.z + ev.w * ev.w;
            s1 += ev.x * vv.x + ev.y * vv.y + ev.z * vv.z + ev.w * vv.w;
            sl += ev.x * cv.x + ev.y * cv.y + ev.z * cv.z + ev.w * cv.w;
        }
        redA[q * 128 + r] = ss;
        redB[q * 128 + r] = s1;
        redC[q * 128 + r] = sl;
    }
    __syncthreads();

    float li = 0.f;
    if (t < 128) {
        int r = t;
        float ss = redA[r] + redA[128 + r];
        float s1 = redB[r] + redB[128 + r];
        float sl = redC[r] + redC[128 + r];
        float rn = 1.f / fmaxf(sqrtf(ss), 1e-12f);
        float S1 = s1 * rn;
        float slab = sl * rn;
        float S2 = s2row[r] * rn * rn;
        float om = 1.f - slab;
        li = om * om * (998.f / 999.f)
           + ((float)NC - 2.f * S1 + S2) * (1.f / 999.f);
    }
    #pragma unroll
    for (int off = 16; off; off >>= 1)
        li += __shfl_xor_sync(0xffffffffu, li, off);
    if ((t & 31) == 0 && t < 128) lsum[t >> 5] = li;
    __syncthreads();
    if (t == 0) atomicAdd(&g_loss, lsum[0] + lsum[1] + lsum[2] + lsum[3]);
}

// ---------------------------------------------------------------------------
__global__ void k_final(float* out) {
    if (threadIdx.x == 0) out[0] = g_loss * (1.f / (float)NROWS);
}

// ---------------------------------------------------------------------------
extern "C" void kernel_launch(void* const* d_in, const int* in_sizes, int n_in,
                              void* d_out, int out_size) {
    const float* emb = (const float*)d_in[0];
    const int* labels = (const int*)d_in[1];
    float* out = (float*)d_out;

    const int smem_bytes = (MROWS * EP + 256 * MP + 256 + 128
                            + 3 * 256 + 128 + 8) * 4;
    cudaFuncSetAttribute(k_main, cudaFuncAttributeMaxDynamicSharedMemorySize,
                         smem_bytes);

    k_zero<<<4096, 256>>>();
    k_normacc<<<NROWS / 8, 256>>>(emb, labels);
    k_centers<<<NC, 256>>>();
    k_M<<<dim3(4, 4, 16), 256>>>();
    k_main<<<NROWS / MROWS, TPB, smem_bytes>>>(emb, labels);
    k_final<<<1, 32>>>(out);
}

// round 6
// speedup vs baseline: 3.2918x; 1.0127x over previous
#include <cuda_runtime.h>
#include <math.h>
#include <stdint.h>

#define NROWS 65536
#define D 256
#define NC 1000
#define NCP 1024
#define MROWS 128
#define TPB 256
#define EBP 132     // Ebf pitch in 32-bit words (132%32=4 -> conflict-free A frags)
#define MBP 72      // Msbf pitch in 32-bit words (72%32=8 -> conflict-free B frags)
#define NREP 4      // g_sums replicas

// ---------------- device scratch ----------------
__device__ float g_sums[NREP * NC * D];
__device__ float g_counts[NREP * NC];
__device__ float g_chat[NCP * D];
__device__ float g_v[D];
__device__ float g_M[D * D];
__device__ float g_loss;

__device__ __forceinline__ uint32_t pack_bf16(float lo, float hi) {
    uint32_t r;
    asm("cvt.rn.bf16x2.f32 %0, %1, %2;" : "=r"(r) : "f"(hi), "f"(lo));
    return r;
}
__device__ __forceinline__ void red_v4(float* p, float a, float b, float c, float d) {
    asm volatile("red.global.add.v4.f32 [%0], {%1,%2,%3,%4};"
                 :: "l"(p), "f"(a), "f"(b), "f"(c), "f"(d) : "memory");
}

// ---------------------------------------------------------------------------
__global__ void k_zero() {
    int i = blockIdx.x * 256 + threadIdx.x;   // grid 4096*256
    if (i < NREP * NC * D) g_sums[i] = 0.f;
    if (i < NCP * D) g_chat[i] = 0.f;
    if (i < D * D) g_M[i] = 0.f;
    if (i < NREP * NC) g_counts[i] = 0.f;
    if (i < D) g_v[i] = 0.f;
    if (i == 0) g_loss = 0.f;
}

// ---------------------------------------------------------------------------
__global__ void k_normacc(const float* __restrict__ emb,
                          const int* __restrict__ labels) {
    int warp = threadIdx.x >> 5, lane = threadIdx.x & 31;
    int row = blockIdx.x * 8 + warp;
    const float* e = emb + (size_t)row * D;

    float4 x0 = *(const float4*)(e + lane * 4);
    float4 x1 = *(const float4*)(e + 128 + lane * 4);
    float ss = x0.x * x0.x + x0.y * x0.y + x0.z * x0.z + x0.w * x0.w
             + x1.x * x1.x + x1.y * x1.y + x1.z * x1.z + x1.w * x1.w;
    #pragma unroll
    for (int off = 16; off; off >>= 1)
        ss += __shfl_xor_sync(0xffffffffu, ss, off);

    float rn = 1.f / fmaxf(sqrtf(ss), 1e-12f);
    int lab = labels[row];
    int rep = (row >> 3) & (NREP - 1);
    float* dst = g_sums + ((size_t)rep * NC + lab) * D;
    red_v4(dst + lane * 4,       x0.x * rn, x0.y * rn, x0.z * rn, x0.w * rn);
    red_v4(dst + 128 + lane * 4, x1.x * rn, x1.y * rn, x1.z * rn, x1.w * rn);
    if (lane == 0) atomicAdd(&g_counts[rep * NC + lab], 1.f);
}

// ---------------------------------------------------------------------------
__global__ void k_centers() {
    int c = blockIdx.x, t = threadIdx.x;
    float cnt = g_counts[c] + g_counts[NC + c]
              + g_counts[2 * NC + c] + g_counts[3 * NC + c];
    float s = g_sums[(size_t)c * D + t]
            + g_sums[(size_t)(NC + c) * D + t]
            + g_sums[(size_t)(2 * NC + c) * D + t]
            + g_sums[(size_t)(3 * NC + c) * D + t];
    float center = s / fmaxf(cnt, 1.f);

    float ss = center * center;
    #pragma unroll
    for (int off = 16; off; off >>= 1)
        ss += __shfl_xor_sync(0xffffffffu, ss, off);
    __shared__ float wsum[8];
    __shared__ float denom_s;
    if ((t & 31) == 0) wsum[t >> 5] = ss;
    __syncthreads();
    if (t == 0) {
        float tot = 0.f;
        #pragma unroll
        for (int w = 0; w < 8; w++) tot += wsum[w];
        denom_s = fmaxf(sqrtf(tot), 1e-8f);
    }
    __syncthreads();
    float ch = center / denom_s;
    g_chat[(size_t)c * D + t] = ch;
    atomicAdd(&g_v[t], ch);
}

// ---------------------------------------------------------------------------
// M = Chat^T Chat (K=1024 padded). Tiled K-split GEMM, atomicAdd epilogue.
__global__ __launch_bounds__(256) void k_M() {
    __shared__ float As[16][64];
    __shared__ float Bs[16][64];
    int t = threadIdx.x;
    int tx = t & 15, ty = t >> 4;
    int cb = blockIdx.x * 64;
    int rb = blockIdx.y * 64;
    int k0 = blockIdx.z * 64;

    float acc[4][4] = {};
    #pragma unroll 1
    for (int kc = 0; kc < 4; kc++) {
        __syncthreads();
        {
            int idx = t;
            int kk = idx >> 4, c4 = (idx & 15) << 2;
            const float* src = g_chat + (size_t)(k0 + kc * 16 + kk) * D;
            *(float4*)&As[kk][c4] = *(const float4*)(src + rb + c4);
            *(float4*)&Bs[kk][c4] = *(const float4*)(src + cb + c4);
        }
        __syncthreads();
        #pragma unroll
        for (int kk = 0; kk < 16; kk++) {
            float a[4], b[4];
            *(float4*)a = *(float4*)&As[kk][ty * 4];
            *(float4*)b = *(float4*)&Bs[kk][tx * 4];
            #pragma unroll
            for (int i = 0; i < 4; i++)
                #pragma unroll
                for (int j = 0; j < 4; j++)
                    acc[i][j] += a[i] * b[j];
        }
    }
    #pragma unroll
    for (int i = 0; i < 4; i++)
        #pragma unroll
        for (int j = 0; j < 4; j++)
            atomicAdd(&g_M[(size_t)(rb + ty * 4 + i) * D + cb + tx * 4 + j],
                      acc[i][j]);
}

// ---------------------------------------------------------------------------
// Main fused kernel. T = E*M via mma.sync bf16 m16n8k16 (tensor pipe).
// E kept only as packed bf16 in smem; f32 reads come from global (L2-hot).
__global__ __launch_bounds__(TPB, 2)
void k_main(const float* __restrict__ emb, const int* __restrict__ labels) {
    extern __shared__ float sh[];
    uint32_t* Ebf  = (uint32_t*)sh;            // 128*EBP = 16896 words
    uint32_t* Msbf = Ebf + MROWS * EBP;        // 128*MBP = 9216 words
    float* vsh   = (float*)(Msbf + 128 * MBP); // 256
    float* s2row = vsh + 256;                  // 128
    float* redA  = s2row + 128;                // 256
    float* redB  = redA + 256;                 // 256
    float* redC  = redB + 256;                 // 256
    int*   labsh = (int*)(redC + 256);         // 128
    float* lsum  = (float*)(labsh + 128);      // 8

    int t = threadIdx.x;
    int w = t >> 5, lane = t & 31;
    int g = lane >> 2, j = lane & 3;           // groupID, threadID_in_group
    int rb = (w & 3) * 32;                     // warp row base (0..96)
    int nb = (w >> 2) * 32;                    // warp col base within 64-chunk
    int row0 = blockIdx.x * MROWS;

    // Load E tile [128 x 256] -> packed bf16 (pairs along K)
    #pragma unroll
    for (int i = 0; i < 32; i++) {
        int idx = t + i * TPB;                 // float4 slot 0..8191
        int r = idx >> 6, c = (idx & 63) << 2;
        float4 x = *(const float4*)(emb + (size_t)(row0 + r) * D + c);
        uint2 p;
        p.x = pack_bf16(x.x, x.y);
        p.y = pack_bf16(x.z, x.w);
        *(uint2*)(Ebf + r * EBP + (c >> 1)) = p;
    }
    if (t < 128) labsh[t] = labels[row0 + t];
    if (t < 128) s2row[t] = 0.f;
    vsh[t] = g_v[t];

    float s2p[4] = {0.f, 0.f, 0.f, 0.f};       // rows rb+g, +8, +16, +24

    #pragma unroll 1
    for (int dc = 0; dc < 4; dc++) {
        __syncthreads();
        // Stage M chunk cols [dc*64, dc*64+64) as packed bf16 [kpair][n]
        #pragma unroll
        for (int i = 0; i < 8; i++) {
            int idx = t + i * TPB;             // 0..2047
            int kp = idx >> 4, c4 = (idx & 15) << 2;
            const float* m0 = g_M + (size_t)(2 * kp) * D + dc * 64 + c4;
            float4 r0 = *(const float4*)m0;
            float4 r1 = *(const float4*)(m0 + D);
            uint4 pw;
            pw.x = pack_bf16(r0.x, r1.x);
            pw.y = pack_bf16(r0.y, r1.y);
            pw.z = pack_bf16(r0.z, r1.z);
            pw.w = pack_bf16(r0.w, r1.w);
            *(uint4*)(Msbf + kp * MBP + c4) = pw;
        }
        __syncthreads();

        float acc[2][4][4] = {};
        #pragma unroll 2
        for (int ks = 0; ks < 16; ks++) {      // K=16 per step
            int kp = ks * 8;
            uint32_t a[2][4];
            #pragma unroll
            for (int mt = 0; mt < 2; mt++) {
                const uint32_t* ar = Ebf + (rb + mt * 16 + g) * EBP + kp + j;
                a[mt][0] = ar[0];
                a[mt][1] = ar[8 * EBP];
                a[mt][2] = ar[4];
                a[mt][3] = ar[8 * EBP + 4];
            }
            #pragma unroll
            for (int nt = 0; nt < 4; nt++) {
                uint32_t b0 = Msbf[(kp + j) * MBP + nb + nt * 8 + g];
                uint32_t b1 = Msbf[(kp + 4 + j) * MBP + nb + nt * 8 + g];
                #pragma unroll
                for (int mt = 0; mt < 2; mt++) {
                    asm volatile(
                        "mma.sync.aligned.m16n8k16.row.col.f32.bf16.bf16.f32 "
                        "{%0,%1,%2,%3}, {%4,%5,%6,%7}, {%8,%9}, {%0,%1,%2,%3};"
                        : "+f"(acc[mt][nt][0]), "+f"(acc[mt][nt][1]),
                          "+f"(acc[mt][nt][2]), "+f"(acc[mt][nt][3])
                        : "r"(a[mt][0]), "r"(a[mt][1]), "r"(a[mt][2]), "r"(a[mt][3]),
                          "r"(b0), "r"(b1));
                }
            }
        }
        // Fold T-chunk into s2 partials: s2p += T[r][c]*E[r][c] (E from global)
        #pragma unroll
        for (int mt = 0; mt < 2; mt++) {
            #pragma unroll
            for (int nt = 0; nt < 4; nt++) {
                int c = dc * 64 + nb + nt * 8 + 2 * j;
                int r0 = rb + mt * 16 + g;
                float2 e0 = *(const float2*)(emb + (size_t)(row0 + r0) * D + c);
                float2 e1 = *(const float2*)(emb + (size_t)(row0 + r0 + 8) * D + c);
                s2p[mt * 2 + 0] += acc[mt][nt][0] * e0.x + acc[mt][nt][1] * e0.y;
                s2p[mt * 2 + 1] += acc[mt][nt][2] * e1.x + acc[mt][nt][3] * e1.y;
            }
        }
    }

    // Reduce s2 partials across the 4 lanes of each group (same rows)
    #pragma unroll
    for (int i = 0; i < 4; i++) {
        float v = s2p[i];
        v += __shfl_xor_sync(0xffffffffu, v, 1);
        v += __shfl_xor_sync(0xffffffffu, v, 2);
        s2p[i] = v;
    }
    if (j == 0) {
        atomicAdd(&s2row[rb + g],      s2p[0]);
        atomicAdd(&s2row[rb + g + 8],  s2p[1]);
        atomicAdd(&s2row[rb + 16 + g], s2p[2]);
        atomicAdd(&s2row[rb + 24 + g], s2p[3]);
    }

    // Per-row dots: ss, e.v, e.chat[label]  (2 threads per row, 128 cols each)
    {
        int r = t & 127, q = t >> 7;
        const float* er = emb + (size_t)(row0 + r) * D + q * 128;
        const float* vr = vsh + q * 128;
        const float* cr = g_chat + (size_t)labsh[r] * D + q * 128;
        float ss = 0.f, s1 = 0.f, sl = 0.f;
        #pragma unroll
        for (int m = 0; m < 32; m++) {
            float4 ev = *(const float4*)(er + m * 4);
            float4 vv = *(const float4*)(vr + m * 4);
            float4 cv = *(const float4*)(cr + m * 4);
            ss += ev.x * ev.x + ev.y * ev.y + ev.z * ev.z + ev.w * ev.w;
            s1 += ev.x * vv.x + ev.y * vv.y + ev.z * vv.z + ev.w * vv.w;
            sl += ev.x * cv.x + ev.y * cv.y + ev.z * cv.z + ev.w * cv.w;
        }
        redA[q * 128 + r] = ss;
        redB[q * 128 + r] = s1;
        redC[q * 128 + r] = sl;
    }
    __syncthreads();

    float li = 0.f;
    if (t < 128) {
        int r = t;
        float ss = redA[r] + redA[128 + r];
        float s1 = redB[r] + redB[128 + r];
        float sl = redC[r] + redC[128 + r];
        float rn = 1.f / fmaxf(sqrtf(ss), 1e-12f);
        float S1 = s1 * rn;
        float slab = sl * rn;
        float S2 = s2row[r] * rn * rn;
        float om = 1.f - slab;
        li = om * om * (998.f / 999.f)
           + ((float)NC - 2.f * S1 + S2) * (1.f / 999.f);
    }
    #pragma unroll
    for (int off = 16; off; off >>= 1)
        li += __shfl_xor_sync(0xffffffffu, li, off);
    if ((t & 31) == 0 && t < 128) lsum[t >> 5] = li;
    __syncthreads();
    if (t == 0) atomicAdd(&g_loss, lsum[0] + lsum[1] + lsum[2] + lsum[3]);
}

// ---------------------------------------------------------------------------
__global__ void k_final(float* out) {
    if (threadIdx.x == 0) out[0] = g_loss * (1.f / (float)NROWS);
}

// ---------------------------------------------------------------------------
extern "C" void kernel_launch(void* const* d_in, const int* in_sizes, int n_in,
                              void* d_out, int out_size) {
    const float* emb = (const float*)d_in[0];
    const int* labels = (const int*)d_in[1];
    float* out = (float*)d_out;

    const int smem_bytes = (MROWS * EBP + 128 * MBP) * 4
                         + (256 + 128 + 3 * 256 + 128 + 8) * 4;
    cudaFuncSetAttribute(k_main, cudaFuncAttributeMaxDynamicSharedMemorySize,
                         smem_bytes);

    k_zero<<<4096, 256>>>();
    k_normacc<<<NROWS / 8, 256>>>(emb, labels);
    k_centers<<<NC, 256>>>();
    k_M<<<dim3(4, 4, 16), 256>>>();
    k_main<<<NROWS / MROWS, TPB, smem_bytes>>>(emb, labels);
    k_final<<<1, 32>>>(out);
}

// round 7
// speedup vs baseline: 4.3552x; 1.3230x over previous
#include <cuda_runtime.h>
#include <math.h>
#include <stdint.h>

#define NROWS 65536
#define D 256
#define NC 1000
#define NCP 1024
#define MROWS 128
#define TPB 256
#define EBP 132     // Ebf pitch in 32-bit words (132%32=4 -> conflict-free)
#define MBP 72      // Msbf pitch in 32-bit words (72%32=8 -> conflict-free)
#define NREP 8      // g_sums replicas

// ---------------- device scratch ----------------
__device__ float g_sums[NREP * NC * D];
__device__ float g_counts[NREP * NC];
__device__ float g_chat[NCP * D];
__device__ float g_v[D];
__device__ float g_M[D * D];
__device__ float g_loss;

__device__ __forceinline__ uint32_t pack_bf16(float lo, float hi) {
    uint32_t r;
    asm("cvt.rn.bf16x2.f32 %0, %1, %2;" : "=r"(r) : "f"(hi), "f"(lo));
    return r;
}
__device__ __forceinline__ float2 unpack_bf16(uint32_t w) {
    float2 f;
    f.x = __uint_as_float(w << 16);
    f.y = __uint_as_float(w & 0xffff0000u);
    return f;
}
__device__ __forceinline__ void red_v4(float* p, float a, float b, float c, float d) {
    asm volatile("red.global.add.v4.f32 [%0], {%1,%2,%3,%4};"
                 :: "l"(p), "f"(a), "f"(b), "f"(c), "f"(d) : "memory");
}

// ---------------------------------------------------------------------------
__global__ void k_zero() {
    int i = blockIdx.x * 256 + threadIdx.x;   // grid 8192*256
    if (i < NREP * NC * D) g_sums[i] = 0.f;
    if (i < NCP * D) g_chat[i] = 0.f;
    if (i < D * D) g_M[i] = 0.f;
    if (i < NREP * NC) g_counts[i] = 0.f;
    if (i < D) g_v[i] = 0.f;
    if (i == 0) g_loss = 0.f;
}

// ---------------------------------------------------------------------------
__global__ void k_normacc(const float* __restrict__ emb,
                          const int* __restrict__ labels) {
    int warp = threadIdx.x >> 5, lane = threadIdx.x & 31;
    int row = blockIdx.x * 8 + warp;
    const float* e = emb + (size_t)row * D;

    float4 x0 = *(const float4*)(e + lane * 4);
    float4 x1 = *(const float4*)(e + 128 + lane * 4);
    float ss = x0.x * x0.x + x0.y * x0.y + x0.z * x0.z + x0.w * x0.w
             + x1.x * x1.x + x1.y * x1.y + x1.z * x1.z + x1.w * x1.w;
    #pragma unroll
    for (int off = 16; off; off >>= 1)
        ss += __shfl_xor_sync(0xffffffffu, ss, off);

    float rn = 1.f / fmaxf(sqrtf(ss), 1e-12f);
    int lab = labels[row];
    int rep = (row >> 3) & (NREP - 1);
    float* dst = g_sums + ((size_t)rep * NC + lab) * D;
    red_v4(dst + lane * 4,       x0.x * rn, x0.y * rn, x0.z * rn, x0.w * rn);
    red_v4(dst + 128 + lane * 4, x1.x * rn, x1.y * rn, x1.z * rn, x1.w * rn);
    if (lane == 0) atomicAdd(&g_counts[rep * NC + lab], 1.f);
}

// ---------------------------------------------------------------------------
__global__ void k_centers() {
    int c = blockIdx.x, t = threadIdx.x;
    float cnt = 0.f, s = 0.f;
    #pragma unroll
    for (int rp = 0; rp < NREP; rp++) {
        cnt += g_counts[rp * NC + c];
        s += g_sums[((size_t)rp * NC + c) * D + t];
    }
    float center = s / fmaxf(cnt, 1.f);

    float ss = center * center;
    #pragma unroll
    for (int off = 16; off; off >>= 1)
        ss += __shfl_xor_sync(0xffffffffu, ss, off);
    __shared__ float wsum[8];
    __shared__ float denom_s;
    if ((t & 31) == 0) wsum[t >> 5] = ss;
    __syncthreads();
    if (t == 0) {
        float tot = 0.f;
        #pragma unroll
        for (int w = 0; w < 8; w++) tot += wsum[w];
        denom_s = fmaxf(sqrtf(tot), 1e-8f);
    }
    __syncthreads();
    float ch = center / denom_s;
    g_chat[(size_t)c * D + t] = ch;
    atomicAdd(&g_v[t], ch);
}

// ---------------------------------------------------------------------------
// M = Chat^T Chat (K=1024 padded). Tiled K-split GEMM, atomicAdd epilogue.
__global__ __launch_bounds__(256) void k_M() {
    __shared__ float As[16][64];
    __shared__ float Bs[16][64];
    int t = threadIdx.x;
    int tx = t & 15, ty = t >> 4;
    int cb = blockIdx.x * 64;
    int rb = blockIdx.y * 64;
    int k0 = blockIdx.z * 64;

    float acc[4][4] = {};
    #pragma unroll 1
    for (int kc = 0; kc < 4; kc++) {
        __syncthreads();
        {
            int idx = t;
            int kk = idx >> 4, c4 = (idx & 15) << 2;
            const float* src = g_chat + (size_t)(k0 + kc * 16 + kk) * D;
            *(float4*)&As[kk][c4] = *(const float4*)(src + rb + c4);
            *(float4*)&Bs[kk][c4] = *(const float4*)(src + cb + c4);
        }
        __syncthreads();
        #pragma unroll
        for (int kk = 0; kk < 16; kk++) {
            float a[4], b[4];
            *(float4*)a = *(float4*)&As[kk][ty * 4];
            *(float4*)b = *(float4*)&Bs[kk][tx * 4];
            #pragma unroll
            for (int i = 0; i < 4; i++)
                #pragma unroll
                for (int j = 0; j < 4; j++)
                    acc[i][j] += a[i] * b[j];
        }
    }
    #pragma unroll
    for (int i = 0; i < 4; i++)
        #pragma unroll
        for (int j = 0; j < 4; j++)
            atomicAdd(&g_M[(size_t)(rb + ty * 4 + i) * D + cb + tx * 4 + j],
                      acc[i][j]);
}

// ---------------------------------------------------------------------------
// Main fused kernel. T = E*M via mma.sync bf16 m16n8k16. All post-GEMM reads
// (fold + per-row dots) come from the bf16 smem tile (exact unpack to f32).
__global__ __launch_bounds__(TPB, 2)
void k_main(const float* __restrict__ emb, const int* __restrict__ labels) {
    extern __shared__ float sh[];
    uint32_t* Ebf  = (uint32_t*)sh;            // 128*EBP = 16896 words
    uint32_t* Msbf = Ebf + MROWS * EBP;        // 128*MBP = 9216 words
    float* vsh   = (float*)(Msbf + 128 * MBP); // 256
    float* s2row = vsh + 256;                  // 128
    float* redA  = s2row + 128;                // 256
    float* redB  = redA + 256;                 // 256
    float* redC  = redB + 256;                 // 256
    int*   labsh = (int*)(redC + 256);         // 128
    float* lsum  = (float*)(labsh + 128);      // 8

    int t = threadIdx.x;
    int w = t >> 5, lane = t & 31;
    int g = lane >> 2, j = lane & 3;           // groupID, threadID_in_group
    int rb = (w & 3) * 32;                     // warp row base (0..96)
    int nb = (w >> 2) * 32;                    // warp col base within 64-chunk
    int row0 = blockIdx.x * MROWS;

    // Load E tile [128 x 256] -> packed bf16 (pairs along K)
    #pragma unroll
    for (int i = 0; i < 32; i++) {
        int idx = t + i * TPB;                 // float4 slot 0..8191
        int r = idx >> 6, c = (idx & 63) << 2;
        float4 x = *(const float4*)(emb + (size_t)(row0 + r) * D + c);
        uint2 p;
        p.x = pack_bf16(x.x, x.y);
        p.y = pack_bf16(x.z, x.w);
        *(uint2*)(Ebf + r * EBP + (c >> 1)) = p;
    }
    if (t < 128) labsh[t] = labels[row0 + t];
    if (t < 128) s2row[t] = 0.f;
    vsh[t] = g_v[t];

    float s2p[4] = {0.f, 0.f, 0.f, 0.f};       // rows rb+g, +8, +16, +24

    #pragma unroll 1
    for (int dc = 0; dc < 4; dc++) {
        __syncthreads();
        // Stage M chunk cols [dc*64, dc*64+64) as packed bf16 [kpair][n]
        #pragma unroll
        for (int i = 0; i < 8; i++) {
            int idx = t + i * TPB;             // 0..2047
            int kp = idx >> 4, c4 = (idx & 15) << 2;
            const float* m0 = g_M + (size_t)(2 * kp) * D + dc * 64 + c4;
            float4 r0 = *(const float4*)m0;
            float4 r1 = *(const float4*)(m0 + D);
            uint4 pw;
            pw.x = pack_bf16(r0.x, r1.x);
            pw.y = pack_bf16(r0.y, r1.y);
            pw.z = pack_bf16(r0.z, r1.z);
            pw.w = pack_bf16(r0.w, r1.w);
            *(uint4*)(Msbf + kp * MBP + c4) = pw;
        }
        __syncthreads();

        float acc[2][4][4] = {};
        #pragma unroll 2
        for (int ks = 0; ks < 16; ks++) {      // K=16 per step
            int kp = ks * 8;
            uint32_t a[2][4];
            #pragma unroll
            for (int mt = 0; mt < 2; mt++) {
                const uint32_t* ar = Ebf + (rb + mt * 16 + g) * EBP + kp + j;
                a[mt][0] = ar[0];
                a[mt][1] = ar[8 * EBP];
                a[mt][2] = ar[4];
                a[mt][3] = ar[8 * EBP + 4];
            }
            #pragma unroll
            for (int nt = 0; nt < 4; nt++) {
                uint32_t b0 = Msbf[(kp + j) * MBP + nb + nt * 8 + g];
                uint32_t b1 = Msbf[(kp + 4 + j) * MBP + nb + nt * 8 + g];
                #pragma unroll
                for (int mt = 0; mt < 2; mt++) {
                    asm volatile(
                        "mma.sync.aligned.m16n8k16.row.col.f32.bf16.bf16.f32 "
                        "{%0,%1,%2,%3}, {%4,%5,%6,%7}, {%8,%9}, {%0,%1,%2,%3};"
                        : "+f"(acc[mt][nt][0]), "+f"(acc[mt][nt][1]),
                          "+f"(acc[mt][nt][2]), "+f"(acc[mt][nt][3])
                        : "r"(a[mt][0]), "r"(a[mt][1]), "r"(a[mt][2]), "r"(a[mt][3]),
                          "r"(b0), "r"(b1));
                }
            }
        }
        // Fold T-chunk into s2 partials from bf16 smem E (conflict-free LDS.32)
        #pragma unroll
        for (int mt = 0; mt < 2; mt++) {
            #pragma unroll
            for (int nt = 0; nt < 4; nt++) {
                int wc = (dc * 64 + nb + nt * 8) / 2 + j;   // word index (pair)
                int r0 = rb + mt * 16 + g;
                float2 e0 = unpack_bf16(Ebf[r0 * EBP + wc]);
                float2 e1 = unpack_bf16(Ebf[(r0 + 8) * EBP + wc]);
                s2p[mt * 2 + 0] += acc[mt][nt][0] * e0.x + acc[mt][nt][1] * e0.y;
                s2p[mt * 2 + 1] += acc[mt][nt][2] * e1.x + acc[mt][nt][3] * e1.y;
            }
        }
    }

    // Reduce s2 partials across the 4 lanes of each group (same rows)
    #pragma unroll
    for (int i = 0; i < 4; i++) {
        float v = s2p[i];
        v += __shfl_xor_sync(0xffffffffu, v, 1);
        v += __shfl_xor_sync(0xffffffffu, v, 2);
        s2p[i] = v;
    }
    if (j == 0) {
        atomicAdd(&s2row[rb + g],      s2p[0]);
        atomicAdd(&s2row[rb + g + 8],  s2p[1]);
        atomicAdd(&s2row[rb + 16 + g], s2p[2]);
        atomicAdd(&s2row[rb + 24 + g], s2p[3]);
    }

    // Per-row dots from bf16 smem E: ss, e.v, e.chat[label]
    {
        int r = t & 127, q = t >> 7;
        const uint32_t* er = Ebf + r * EBP + q * 64;   // 64 words = 128 cols
        const float* vr = vsh + q * 128;
        const float* cr = g_chat + (size_t)labsh[r] * D + q * 128;
        float ss = 0.f, s1 = 0.f, sl = 0.f;
        #pragma unroll
        for (int m = 0; m < 16; m++) {
            uint4 ew = *(const uint4*)(er + m * 4);    // cols 8m..8m+7
            float2 e0 = unpack_bf16(ew.x), e1 = unpack_bf16(ew.y);
            float2 e2 = unpack_bf16(ew.z), e3 = unpack_bf16(ew.w);
            float4 v0 = *(const float4*)(vr + m * 8);
            float4 v1 = *(const float4*)(vr + m * 8 + 4);
            float4 c0 = *(const float4*)(cr + m * 8);
            float4 c1 = *(const float4*)(cr + m * 8 + 4);
            ss += e0.x * e0.x + e0.y * e0.y + e1.x * e1.x + e1.y * e1.y
                + e2.x * e2.x + e2.y * e2.y + e3.x * e3.x + e3.y * e3.y;
            s1 += e0.x * v0.x + e0.y * v0.y + e1.x * v0.z + e1.y * v0.w
                + e2.x * v1.x + e2.y * v1.y + e3.x * v1.z + e3.y * v1.w;
            sl += e0.x * c0.x + e0.y * c0.y + e1.x * c0.z + e1.y * c0.w
                + e2.x * c1.x + e2.y * c1.y + e3.x * c1.z + e3.y * c1.w;
        }
        redA[q * 128 + r] = ss;
        redB[q * 128 + r] = s1;
        redC[q * 128 + r] = sl;
    }
    __syncthreads();

    float li = 0.f;
    if (t < 128) {
        int r = t;
        float ss = redA[r] + redA[128 + r];
        float s1 = redB[r] + redB[128 + r];
        float sl = redC[r] + redC[128 + r];
        float rn = 1.f / fmaxf(sqrtf(ss), 1e-12f);
        float S1 = s1 * rn;
        float slab = sl * rn;
        float S2 = s2row[r] * rn * rn;
        float om = 1.f - slab;
        li = om * om * (998.f / 999.f)
           + ((float)NC - 2.f * S1 + S2) * (1.f / 999.f);
    }
    #pragma unroll
    for (int off = 16; off; off >>= 1)
        li += __shfl_xor_sync(0xffffffffu, li, off);
    if ((t & 31) == 0 && t < 128) lsum[t >> 5] = li;
    __syncthreads();
    if (t == 0) atomicAdd(&g_loss, lsum[0] + lsum[1] + lsum[2] + lsum[3]);
}

// ---------------------------------------------------------------------------
__global__ void k_final(float* out) {
    if (threadIdx.x == 0) out[0] = g_loss * (1.f / (float)NROWS);
}

// ---------------------------------------------------------------------------
extern "C" void kernel_launch(void* const* d_in, const int* in_sizes, int n_in,
                              void* d_out, int out_size) {
    const float* emb = (const float*)d_in[0];
    const int* labels = (const int*)d_in[1];
    float* out = (float*)d_out;

    const int smem_bytes = (MROWS * EBP + 128 * MBP) * 4
                         + (256 + 128 + 3 * 256 + 128 + 8) * 4;
    cudaFuncSetAttribute(k_main, cudaFuncAttributeMaxDynamicSharedMemorySize,
                         smem_bytes);

    k_zero<<<8192, 256>>>();
    k_normacc<<<NROWS / 8, 256>>>(emb, labels);
    k_centers<<<NC, 256>>>();
    k_M<<<dim3(4, 4, 16), 256>>>();
    k_main<<<NROWS / MROWS, TPB, smem_bytes>>>(emb, labels);
    k_final<<<1, 32>>>(out);
}